// round 16
// baseline (speedup 1.0000x reference)
#include <cuda_runtime.h>
#include <cuda_fp16.h>

#define B_  2
#define L_  24
#define C_  16
#define H_  64
#define W_  64
#define HW_ 4096
#define KCH 12

// Packed-fp16 channel-grouped scratch: [B*L][2 halves][HW] x uint4
// (8 channels = 16 bytes per pixel per half).
__device__ uint4 g_imgH[(size_t)B_ * L_ * 2 * HW_];
// Cumulative flow scratch: [B][L][HW] float2 (x,y per pixel).
__device__ float2 g_cum[(size_t)B_ * L_ * HW_];

// (t, k0) chunk table, chunks of <=KCH k's, sorted DESCENDING by length so the
// longest blocks get the lowest block ids (start in wave 1; drain tail short).
__constant__ short2 g_chunks[36] = {
    {11,0},{12,0},{13,0},{14,0},{15,0},{16,0},{17,0},{18,0},{19,0},{20,0},
    {21,0},{22,0},{23,0},{23,12},
    {10,0},{22,12},{9,0},{21,12},{8,0},{20,12},{7,0},{19,12},{6,0},{18,12},
    {5,0},{17,12},{4,0},{16,12},{3,0},{15,12},{2,0},{14,12},{1,0},{13,12},
    {0,0},{12,12}
};

union U4H8 {
    uint4   u;
    __half2 h[4];
};

// Merged prologue.
//   blocks [0, 384):    NCHW -> packed-fp16 8-channel transpose (4 pix/thread)
//   blocks [384, 416):  flow cumsum along L
//   blocks [416, 1952): zero the atomic region of out (t >= KCH), 1 uint4/thread
__global__ __launch_bounds__(256) void prep_kernel(
    const float* __restrict__ images,   // [B, L, C, H, W]
    const float* __restrict__ flows,    // [B, L, 2, H, W]
    float* __restrict__ out)            // [B, L, C, H, W]
{
    const int bid = blockIdx.x;
    if (bid < 384) {
        const int id   = bid * 256 + threadIdx.x;
        const int pix4 = (id & 1023) * 4;         // 4-pixel base
        const int half = (id >> 10) & 1;
        const int bl   = id >> 11;                // 0..47
        const float4* src = (const float4*)(images + ((size_t)bl * C_ + half * 8) * HW_ + pix4);
        float4 r[8];
#pragma unroll
        for (int c = 0; c < 8; ++c) r[c] = src[(size_t)c * (HW_ / 4)];

        uint4* dst = g_imgH + ((size_t)bl * 2 + half) * HW_ + pix4;
#pragma unroll
        for (int j = 0; j < 4; ++j) {
            const float* f = (const float*)r;     // r[c] component j = f[c*4 + j]
            U4H8 o;
            o.h[0] = __floats2half2_rn(f[0*4 + j], f[1*4 + j]);
            o.h[1] = __floats2half2_rn(f[2*4 + j], f[3*4 + j]);
            o.h[2] = __floats2half2_rn(f[4*4 + j], f[5*4 + j]);
            o.h[3] = __floats2half2_rn(f[6*4 + j], f[7*4 + j]);
            dst[j] = o.u;
        }
    } else if (bid < 416) {
        const int id  = (bid - 384) * 256 + threadIdx.x;   // 0..8191
        const int pix = id & (HW_ - 1);
        const int b   = id >> 12;
        const float* fp = flows + (size_t)b * L_ * 2 * HW_ + pix;
        float2* cp = g_cum + (size_t)b * L_ * HW_ + pix;
        float sx = 0.f, sy = 0.f;
#pragma unroll
        for (int k = 0; k < L_; ++k) {
            sx += fp[(size_t)k * 2 * HW_];
            sy += fp[(size_t)k * 2 * HW_ + HW_];
            cp[(size_t)k * HW_] = make_float2(sx, sy);
        }
    } else {
        // zero out[b, t>=KCH, :, :] — 3 MB per b = 768 blocks per b
        const int zb    = bid - 416;              // 0..1535
        const int b     = (zb >= 768) ? 1 : 0;
        const int local = zb - b * 768;
        const int idx   = local * 256 + threadIdx.x;      // 0..196607 uint4
        uint4* p = (uint4*)(out + ((size_t)b * L_ + KCH) * C_ * HW_);
        p[idx] = make_uint4(0u, 0u, 0u, 0u);
    }
}

// acc[0..7] += s * unpack_fp16x8(v)
__device__ __forceinline__ void fmah8(float acc[8], float s, uint4 v) {
    const __half2* hp = reinterpret_cast<const __half2*>(&v);
    float2 f0 = __half22float2(hp[0]);
    float2 f1 = __half22float2(hp[1]);
    float2 f2 = __half22float2(hp[2]);
    float2 f3 = __half22float2(hp[3]);
    acc[0] += s * f0.x; acc[1] += s * f0.y;
    acc[2] += s * f1.x; acc[3] += s * f1.y;
    acc[4] += s * f2.x; acc[5] += s * f2.y;
    acc[6] += s * f3.x; acc[7] += s * f3.y;
}

// One bilinear-tap step for 8 channels. k-indexed addressing (independent
// unrolled iterations); SEPARABLE validity masking: w*valid = (wx*vx)(wy*vy),
// so mask the four 1-D weights once with predicated selects.
__device__ __forceinline__ void gsp_step(
    int k, int w, int h, float2 cumt, const float2* __restrict__ cumb,
    const uint4* __restrict__ gbase, float acc[8])
{
    const float2 ckf = cumb[(size_t)k * HW_];
    float relx = cumt.x - ckf.x;   // exactly 0 when k==t
    float rely = cumt.y - ckf.y;

    // align_corners=False: base grid == pixel centers
    float ix = (float)w + 32.f * relx;
    ix -= 64.f * floorf((ix + 0.5f) * 0.015625f);   // wrap x into [-0.5, 63.5)
    float iy = (float)h + 32.f * rely;

    int x0 = __float2int_rd(ix);   // in [-1, 63] by construction
    int y0 = __float2int_rd(iy);
    int y1 = y0 + 1;
    float wx1 = ix - (float)x0,  wy1 = iy - (float)y0;
    float wx0 = 1.f - wx1,       wy0 = 1.f - wy1;

    // separable masking (x1 = x0+1 in [0,64]: only x0<0 / x0==63 invalid)
    wx0 = (x0 >= 0)                ? wx0 : 0.f;
    wx1 = (x0 < W_ - 1)            ? wx1 : 0.f;
    wy0 = ((unsigned)y0 <= H_ - 1) ? wy0 : 0.f;
    wy1 = ((unsigned)y1 <= H_ - 1) ? wy1 : 0.f;

    float w00 = wx0 * wy0, w01 = wx1 * wy0;
    float w10 = wx0 * wy1, w11 = wx1 * wy1;

    int cx0 = max(x0, 0),               cx1 = min(x0 + 1, W_ - 1);
    int cy0 = min(max(y0, 0), H_ - 1),  cy1 = min(max(y1, 0), H_ - 1);

    const uint4* gk = gbase + (size_t)k * 2 * HW_;
    uint4 v00 = gk[cy0 * W_ + cx0];
    uint4 v01 = gk[cy0 * W_ + cx1];
    uint4 v10 = gk[cy1 * W_ + cx0];
    uint4 v11 = gk[cy1 * W_ + cx1];

    fmah8(acc, w00, v00);
    fmah8(acc, w01, v01);
    fmah8(acc, w10, v10);
    fmah8(acc, w11, v11);
}

// out[b,t,c,h,w] += sum_{k in chunk} bilinear taps (8 channels per thread).
// Grid = (pixtile, b*2+half, chunk-desc-sorted); <= KCH iterations per block.
__global__ __launch_bounds__(256, 6) void gsp_kernel(
    float* __restrict__ out)            // [B, L, C, H, W]
{
    const int b    = blockIdx.y >> 1;
    const int half = blockIdx.y & 1;          // 0 -> c0..7; 1 -> c8..15
    const short2 ck_ = g_chunks[blockIdx.z];
    const int t    = ck_.x;
    const int k0   = ck_.y;
    const int kend = min(k0 + KCH, t + 1);
    const int pix  = blockIdx.x * blockDim.x + threadIdx.x;
    const int h    = pix >> 6;
    const int w    = pix & 63;

    float acc[8];
#pragma unroll
    for (int c = 0; c < 8; ++c) acc[c] = 0.f;

    const float2* cumb = g_cum + (size_t)b * L_ * HW_ + pix;
    const float2 cumt = cumb[(size_t)t * HW_];
    const uint4* gbase = g_imgH + ((size_t)b * L_ * 2 + half) * HW_;

#pragma unroll 4
    for (int k = k0; k < kend; ++k)
        gsp_step(k, w, h, cumt, cumb, gbase, acc);

    float* op = out + (((size_t)b * L_ + t) * C_ + half * 8) * HW_ + pix;
    if (t < KCH) {   // single writer: plain stores
#pragma unroll
        for (int c = 0; c < 8; ++c) op[(size_t)c * HW_] = acc[c];
    } else {
#pragma unroll
        for (int c = 0; c < 8; ++c) atomicAdd(op + (size_t)c * HW_, acc[c]);
    }
}

extern "C" void kernel_launch(void* const* d_in, const int* in_sizes, int n_in,
                              void* d_out, int out_size)
{
    const float* flows  = (const float*)d_in[0];   // [2,24,2,64,64]
    const float* images = (const float*)d_in[1];   // [2,24,16,64,64]
    float*       out    = (float*)d_out;           // [2,24,16,64,64]

    prep_kernel<<<1952, 256>>>(images, flows, out); // transpose + cumsum + zero

    dim3 grid(HW_ / 256, B_ * 2, 36);              // (16, 4, 36) — chunk outermost
    gsp_kernel<<<grid, 256>>>(out);
}

// round 17
// speedup vs baseline: 1.0580x; 1.0580x over previous
#include <cuda_runtime.h>
#include <cuda_fp16.h>
#include <cstdint>

#define B_  2
#define L_  24
#define C_  16
#define H_  64
#define W_  64
#define HW_ 4096
#define KCH 12

// Packed-fp16 channel-grouped scratch: [B*L][2 halves][HW] x uint4
// (8 channels = 16 bytes per pixel per half).
__device__ uint4 g_imgH[(size_t)B_ * L_ * 2 * HW_];
// Cumulative flow scratch: [B][L][HW] float2 (x,y per pixel).
__device__ float2 g_cum[(size_t)B_ * L_ * HW_];

// (t, k0) chunk table, chunks of <=KCH k's, sorted DESCENDING by length so the
// longest blocks get the lowest block ids (start in wave 1; drain tail short).
__constant__ short2 g_chunks[36] = {
    {11,0},{12,0},{13,0},{14,0},{15,0},{16,0},{17,0},{18,0},{19,0},{20,0},
    {21,0},{22,0},{23,0},{23,12},
    {10,0},{22,12},{9,0},{21,12},{8,0},{20,12},{7,0},{19,12},{6,0},{18,12},
    {5,0},{17,12},{4,0},{16,12},{3,0},{15,12},{2,0},{14,12},{1,0},{13,12},
    {0,0},{12,12}
};

union U4H8 {
    uint4   u;
    __half2 h[4];
};

// Merged prologue.
//   blocks [0, 384):    NCHW -> packed-fp16 8-channel transpose (4 pix/thread)
//   blocks [384, 416):  flow cumsum along L
//   blocks [416, 1952): zero the atomic region of out (t >= KCH), 1 uint4/thread
__global__ __launch_bounds__(256) void prep_kernel(
    const float* __restrict__ images,   // [B, L, C, H, W]
    const float* __restrict__ flows,    // [B, L, 2, H, W]
    float* __restrict__ out)            // [B, L, C, H, W]
{
    const int bid = blockIdx.x;
    if (bid < 384) {
        const int id   = bid * 256 + threadIdx.x;
        const int pix4 = (id & 1023) * 4;         // 4-pixel base
        const int half = (id >> 10) & 1;
        const int bl   = id >> 11;                // 0..47
        const float4* src = (const float4*)(images + ((size_t)bl * C_ + half * 8) * HW_ + pix4);
        float4 r[8];
#pragma unroll
        for (int c = 0; c < 8; ++c) r[c] = src[(size_t)c * (HW_ / 4)];

        uint4* dst = g_imgH + ((size_t)bl * 2 + half) * HW_ + pix4;
#pragma unroll
        for (int j = 0; j < 4; ++j) {
            const float* f = (const float*)r;     // r[c] component j = f[c*4 + j]
            U4H8 o;
            o.h[0] = __floats2half2_rn(f[0*4 + j], f[1*4 + j]);
            o.h[1] = __floats2half2_rn(f[2*4 + j], f[3*4 + j]);
            o.h[2] = __floats2half2_rn(f[4*4 + j], f[5*4 + j]);
            o.h[3] = __floats2half2_rn(f[6*4 + j], f[7*4 + j]);
            dst[j] = o.u;
        }
    } else if (bid < 416) {
        const int id  = (bid - 384) * 256 + threadIdx.x;   // 0..8191
        const int pix = id & (HW_ - 1);
        const int b   = id >> 12;
        const float* fp = flows + (size_t)b * L_ * 2 * HW_ + pix;
        float2* cp = g_cum + (size_t)b * L_ * HW_ + pix;
        float sx = 0.f, sy = 0.f;
#pragma unroll
        for (int k = 0; k < L_; ++k) {
            sx += fp[(size_t)k * 2 * HW_];
            sy += fp[(size_t)k * 2 * HW_ + HW_];
            cp[(size_t)k * HW_] = make_float2(sx, sy);
        }
    } else {
        // zero out[b, t>=KCH, :, :] — 3 MB per b = 768 blocks per b
        const int zb    = bid - 416;              // 0..1535
        const int b     = (zb >= 768) ? 1 : 0;
        const int local = zb - b * 768;
        const int idx   = local * 256 + threadIdx.x;      // 0..196607 uint4
        uint4* p = (uint4*)(out + ((size_t)b * L_ + KCH) * C_ * HW_);
        p[idx] = make_uint4(0u, 0u, 0u, 0u);
    }
}

// acc2[0..3] (packed f32x2 pairs) += splat(s) * unpack_fp16x8(v)
// Uses Blackwell packed fma.rn.f32x2 — halves the FFMA count per tap.
__device__ __forceinline__ void fmah8(uint64_t acc2[4], float s, uint4 v) {
    uint64_t ws;
    asm("mov.b64 %0, {%1, %1};" : "=l"(ws) : "f"(s));
    const __half2* hp = reinterpret_cast<const __half2*>(&v);
#pragma unroll
    for (int j = 0; j < 4; ++j) {
        float2 f = __half22float2(hp[j]);
        uint64_t fv;
        asm("mov.b64 %0, {%1, %2};" : "=l"(fv) : "f"(f.x), "f"(f.y));
        asm("fma.rn.f32x2 %0, %1, %2, %3;"
            : "=l"(acc2[j]) : "l"(ws), "l"(fv), "l"(acc2[j]));
    }
}

// One bilinear-tap step for 8 channels (one uint4 per corner) — R15 form:
// k-indexed addressing, bool-multiply masking (parallel mask computation).
__device__ __forceinline__ void gsp_step(
    int k, int w, int h, float2 cumt, const float2* __restrict__ cumb,
    const uint4* __restrict__ gbase, uint64_t acc2[4])
{
    const float2 ckf = cumb[(size_t)k * HW_];
    float relx = cumt.x - ckf.x;   // exactly 0 when k==t
    float rely = cumt.y - ckf.y;

    // align_corners=False: base grid == pixel centers
    float ix = (float)w + 32.f * relx;
    ix -= 64.f * floorf((ix + 0.5f) * 0.015625f);   // wrap x into [-0.5, 63.5)
    float iy = (float)h + 32.f * rely;

    float x0f = floorf(ix), y0f = floorf(iy);
    int   x0  = (int)x0f,   y0  = (int)y0f;
    float wx1 = ix - x0f,   wy1 = iy - y0f;
    float wx0 = 1.f - wx1,  wy0 = 1.f - wy1;

    // x0 in [-1, 63] by construction; x1 = x0+1 in [0, 64]
    bool vx0 = (x0 >= 0);
    bool vx1 = (x0 < W_ - 1);
    bool vy0 = (y0 >= 0) && (y0 <= H_ - 1);
    bool vy1 = (y0 >= -1) && (y0 < H_ - 1);

    float w00 = wx0 * wy0 * (float)(vx0 && vy0);
    float w01 = wx1 * wy0 * (float)(vx1 && vy0);
    float w10 = wx0 * wy1 * (float)(vx0 && vy1);
    float w11 = wx1 * wy1 * (float)(vx1 && vy1);

    int cx0 = max(x0, 0),              cx1 = min(x0 + 1, W_ - 1);
    int cy0 = min(max(y0, 0), H_ - 1), cy1 = min(max(y0 + 1, 0), H_ - 1);

    const uint4* gk = gbase + (size_t)k * 2 * HW_;
    uint4 v00 = gk[cy0 * W_ + cx0];
    uint4 v01 = gk[cy0 * W_ + cx1];
    uint4 v10 = gk[cy1 * W_ + cx0];
    uint4 v11 = gk[cy1 * W_ + cx1];

    fmah8(acc2, w00, v00);
    fmah8(acc2, w01, v01);
    fmah8(acc2, w10, v10);
    fmah8(acc2, w11, v11);
}

// out[b,t,c,h,w] += sum_{k in chunk} bilinear taps (8 channels per thread).
// Grid = (pixtile, b*2+half, chunk-desc-sorted); <= KCH iterations per block.
__global__ __launch_bounds__(256, 6) void gsp_kernel(
    float* __restrict__ out)            // [B, L, C, H, W]
{
    const int b    = blockIdx.y >> 1;
    const int half = blockIdx.y & 1;          // 0 -> c0..7; 1 -> c8..15
    const short2 ck_ = g_chunks[blockIdx.z];
    const int t    = ck_.x;
    const int k0   = ck_.y;
    const int kend = min(k0 + KCH, t + 1);
    const int pix  = blockIdx.x * blockDim.x + threadIdx.x;
    const int h    = pix >> 6;
    const int w    = pix & 63;

    uint64_t acc2[4] = {0ull, 0ull, 0ull, 0ull};   // 8 fp32 accumulators, packed

    const float2* cumb = g_cum + (size_t)b * L_ * HW_ + pix;
    const float2 cumt = cumb[(size_t)t * HW_];
    const uint4* gbase = g_imgH + ((size_t)b * L_ * 2 + half) * HW_;

#pragma unroll 4
    for (int k = k0; k < kend; ++k)
        gsp_step(k, w, h, cumt, cumb, gbase, acc2);

    // unpack accumulators
    float a[8];
#pragma unroll
    for (int j = 0; j < 4; ++j)
        asm("mov.b64 {%0, %1}, %2;" : "=f"(a[2*j]), "=f"(a[2*j+1]) : "l"(acc2[j]));

    float* op = out + (((size_t)b * L_ + t) * C_ + half * 8) * HW_ + pix;
    if (t < KCH) {   // single writer: plain stores
#pragma unroll
        for (int c = 0; c < 8; ++c) op[(size_t)c * HW_] = a[c];
    } else {
#pragma unroll
        for (int c = 0; c < 8; ++c) atomicAdd(op + (size_t)c * HW_, a[c]);
    }
}

extern "C" void kernel_launch(void* const* d_in, const int* in_sizes, int n_in,
                              void* d_out, int out_size)
{
    const float* flows  = (const float*)d_in[0];   // [2,24,2,64,64]
    const float* images = (const float*)d_in[1];   // [2,24,16,64,64]
    float*       out    = (float*)d_out;           // [2,24,16,64,64]

    prep_kernel<<<1952, 256>>>(images, flows, out); // transpose + cumsum + zero

    dim3 grid(HW_ / 256, B_ * 2, 36);              // (16, 4, 36) — chunk outermost
    gsp_kernel<<<grid, 256>>>(out);
}